// round 1
// baseline (speedup 1.0000x reference)
#include <cuda_runtime.h>
#include <math.h>

// Problem dims (fixed by the dataset)
#define B_  4
#define S_  2048
#define D_  768
#define H_  12
#define E_  64
#define BS_ (B_ * S_)   // 8192

// Scratch (static device globals: allocation-free per harness rules)
__device__ float g_q[(size_t)B_ * H_ * S_ * E_];
__device__ float g_k[(size_t)B_ * H_ * S_ * E_];
__device__ float g_v[(size_t)B_ * H_ * S_ * E_];
__device__ float g_z[(size_t)BS_ * D_];

// ---------------------------------------------------------------------------
// QKV projection: out[b][h][s][e] = sum_d x[bs][d] * W[h][d][e] + bias[h][e]
// Tiling: 64x64 output tile per block, BK=16, 256 threads, 4x4 per thread.
// Thread (tx,ty) owns rows {ty+16i}, cols {tx+16j}  (strided => conflict-free)
// ---------------------------------------------------------------------------
__global__ void __launch_bounds__(256) qkv_gemm(
    const float* __restrict__ x, const float* __restrict__ W,
    const float* __restrict__ bias, float* __restrict__ out)
{
    __shared__ float As[64][17];   // [row][kk], pad to 17 (odd stride)
    __shared__ float Bs[16][64];   // [kk][e], consecutive reads => no pad

    const int h    = blockIdx.y;
    const int row0 = blockIdx.x * 64;
    const int tid  = threadIdx.x;
    const int tx   = tid & 15, ty = tid >> 4;

    const float* __restrict__ Wh = W + (size_t)h * D_ * E_;
    float acc[4][4] = {};

    for (int k0 = 0; k0 < D_; k0 += 16) {
        {   // load A tile 64x16 (one float4 per thread)
            int r   = tid >> 2;
            int kk4 = (tid & 3) * 4;
            float4 v4 = *reinterpret_cast<const float4*>(&x[(size_t)(row0 + r) * D_ + k0 + kk4]);
            As[r][kk4 + 0] = v4.x; As[r][kk4 + 1] = v4.y;
            As[r][kk4 + 2] = v4.z; As[r][kk4 + 3] = v4.w;
        }
        {   // load B tile 16x64 (one float4 per thread)
            int kk = tid >> 4;
            int e4 = (tid & 15) * 4;
            *reinterpret_cast<float4*>(&Bs[kk][e4]) =
                *reinterpret_cast<const float4*>(&Wh[(size_t)(k0 + kk) * E_ + e4]);
        }
        __syncthreads();
        #pragma unroll
        for (int kk = 0; kk < 16; ++kk) {
            float a[4], bb[4];
            #pragma unroll
            for (int i = 0; i < 4; ++i) a[i]  = As[ty + i * 16][kk];
            #pragma unroll
            for (int j = 0; j < 4; ++j) bb[j] = Bs[kk][tx + j * 16];
            #pragma unroll
            for (int i = 0; i < 4; ++i)
                #pragma unroll
                for (int j = 0; j < 4; ++j) acc[i][j] += a[i] * bb[j];
        }
        __syncthreads();
    }

    #pragma unroll
    for (int i = 0; i < 4; ++i) {
        int row = row0 + ty + i * 16;
        int b   = row / S_, s = row % S_;
        float* orow = out + ((size_t)(b * H_ + h) * S_ + s) * E_;
        #pragma unroll
        for (int j = 0; j < 4; ++j) {
            int e = tx + j * 16;
            orow[e] = acc[i][j] + bias[h * E_ + e];
        }
    }
}

// ---------------------------------------------------------------------------
// Flash attention per (b, h, 64-query tile). Causal. 256 threads.
// Dynamic smem: Q[64][64], KP[64][65] (K tile, then reused for P), V[64][64],
// plus per-row stats m/l/c. Online softmax with unnormalized accumulator.
// ---------------------------------------------------------------------------
__global__ void __launch_bounds__(256) attn_kernel()
{
    extern __shared__ float sm[];
    float* Qs  = sm;                 // 64*64
    float* KPs = Qs + 64 * 64;       // 64*65 (padded: read stride-65 on QK^T)
    float* Vs  = KPs + 64 * 65;      // 64*64
    float* m_s = Vs + 64 * 64;       // 64
    float* l_s = m_s + 64;           // 64
    float* c_s = l_s + 64;           // 64

    const int qt  = blockIdx.x;
    const int h   = blockIdx.y;
    const int b   = blockIdx.z;
    const int tid = threadIdx.x;
    const int tx  = tid & 15, ty = tid >> 4;

    const size_t bh = ((size_t)(b * H_ + h)) * S_ * E_;

    // load Q tile
    for (int idx = tid; idx < 64 * 64; idx += 256) {
        int r = idx >> 6, e = idx & 63;
        Qs[r * 64 + e] = g_q[bh + (size_t)(qt * 64 + r) * E_ + e];
    }
    if (tid < 64) { m_s[tid] = -1e30f; l_s[tid] = 0.f; }

    float o[4][4] = {};
    __syncthreads();

    const float scale = 0.125f;   // 1/sqrt(64)

    for (int jt = 0; jt <= qt; ++jt) {
        // load K, V tiles
        for (int idx = tid; idx < 64 * 64; idx += 256) {
            int r = idx >> 6, e = idx & 63;
            KPs[r * 65 + e] = g_k[bh + (size_t)(jt * 64 + r) * E_ + e];
            Vs [r * 64 + e] = g_v[bh + (size_t)(jt * 64 + r) * E_ + e];
        }
        __syncthreads();

        // S = Q K^T (regs)
        float s[4][4] = {};
        #pragma unroll
        for (int e = 0; e < 64; ++e) {
            float a[4], bb[4];
            #pragma unroll
            for (int i = 0; i < 4; ++i) a[i]  = Qs[(ty + i * 16) * 64 + e];
            #pragma unroll
            for (int j = 0; j < 4; ++j) bb[j] = KPs[(tx + j * 16) * 65 + e];
            #pragma unroll
            for (int i = 0; i < 4; ++i)
                #pragma unroll
                for (int j = 0; j < 4; ++j) s[i][j] += a[i] * bb[j];
        }
        __syncthreads();   // everyone done reading K => can overwrite with P

        // scale + causal mask, write into KP (now P storage)
        #pragma unroll
        for (int i = 0; i < 4; ++i) {
            int iq = ty + i * 16;
            #pragma unroll
            for (int j = 0; j < 4; ++j) {
                int jk = tx + j * 16;
                float val = s[i][j] * scale;
                if (jt == qt && jk > iq) val = -1e30f;
                KPs[iq * 65 + jk] = val;
            }
        }
        __syncthreads();

        // online softmax, one thread per row
        if (tid < 64) {
            float mold = m_s[tid];
            float mx = mold;
            #pragma unroll 8
            for (int j = 0; j < 64; ++j) mx = fmaxf(mx, KPs[tid * 65 + j]);
            float c = __expf(mold - mx);
            float sum = 0.f;
            #pragma unroll 8
            for (int j = 0; j < 64; ++j) {
                float p = __expf(KPs[tid * 65 + j] - mx);
                KPs[tid * 65 + j] = p;
                sum += p;
            }
            l_s[tid] = l_s[tid] * c + sum;
            m_s[tid] = mx;
            c_s[tid] = c;
        }
        __syncthreads();

        // O = O * c + P @ V
        #pragma unroll
        for (int i = 0; i < 4; ++i) {
            float ci = c_s[ty + i * 16];
            #pragma unroll
            for (int j = 0; j < 4; ++j) o[i][j] *= ci;
        }
        #pragma unroll
        for (int j = 0; j < 64; ++j) {
            float a[4], bb[4];
            #pragma unroll
            for (int i = 0; i < 4; ++i)  a[i]  = KPs[(ty + i * 16) * 65 + j];
            #pragma unroll
            for (int jj = 0; jj < 4; ++jj) bb[jj] = Vs[j * 64 + tx + jj * 16];
            #pragma unroll
            for (int i = 0; i < 4; ++i)
                #pragma unroll
                for (int jj = 0; jj < 4; ++jj) o[i][jj] += a[i] * bb[jj];
        }
        __syncthreads();
    }

    // normalize + write z as [bs][h*64+e]
    #pragma unroll
    for (int i = 0; i < 4; ++i) {
        int iq = ty + i * 16;
        float inv_l = 1.0f / l_s[iq];
        #pragma unroll
        for (int j = 0; j < 4; ++j) {
            int e = tx + j * 16;
            g_z[(size_t)(b * S_ + qt * 64 + iq) * D_ + h * E_ + e] = o[i][j] * inv_l;
        }
    }
}

// ---------------------------------------------------------------------------
// Output projection: out[bs][d] = sum_k z[bs][k] * Wo[k][d] + bO[d]
// Wo flattened from [h][e][d] is exactly row-major [768][768].
// ---------------------------------------------------------------------------
__global__ void __launch_bounds__(256) out_proj(
    const float* __restrict__ Wo, const float* __restrict__ bO,
    float* __restrict__ out)
{
    __shared__ float As[64][17];
    __shared__ float Bs[16][64];

    const int n0   = blockIdx.y * 64;
    const int row0 = blockIdx.x * 64;
    const int tid  = threadIdx.x;
    const int tx   = tid & 15, ty = tid >> 4;

    float acc[4][4] = {};

    for (int k0 = 0; k0 < D_; k0 += 16) {
        {
            int r   = tid >> 2;
            int kk4 = (tid & 3) * 4;
            float4 v4 = *reinterpret_cast<const float4*>(&g_z[(size_t)(row0 + r) * D_ + k0 + kk4]);
            As[r][kk4 + 0] = v4.x; As[r][kk4 + 1] = v4.y;
            As[r][kk4 + 2] = v4.z; As[r][kk4 + 3] = v4.w;
        }
        {
            int kk = tid >> 4;
            int e4 = (tid & 15) * 4;
            *reinterpret_cast<float4*>(&Bs[kk][e4]) =
                *reinterpret_cast<const float4*>(&Wo[(size_t)(k0 + kk) * D_ + n0 + e4]);
        }
        __syncthreads();
        #pragma unroll
        for (int kk = 0; kk < 16; ++kk) {
            float a[4], bb[4];
            #pragma unroll
            for (int i = 0; i < 4; ++i) a[i]  = As[ty + i * 16][kk];
            #pragma unroll
            for (int j = 0; j < 4; ++j) bb[j] = Bs[kk][tx + j * 16];
            #pragma unroll
            for (int i = 0; i < 4; ++i)
                #pragma unroll
                for (int j = 0; j < 4; ++j) acc[i][j] += a[i] * bb[j];
        }
        __syncthreads();
    }

    #pragma unroll
    for (int i = 0; i < 4; ++i) {
        int row = row0 + ty + i * 16;
        #pragma unroll
        for (int j = 0; j < 4; ++j) {
            int d = n0 + tx + j * 16;
            out[(size_t)row * D_ + d] = acc[i][j] + bO[d];
        }
    }
}

// ---------------------------------------------------------------------------
extern "C" void kernel_launch(void* const* d_in, const int* in_sizes, int n_in,
                              void* d_out, int out_size)
{
    const float* x  = (const float*)d_in[0];
    const float* WQ = (const float*)d_in[1];
    const float* WK = (const float*)d_in[2];
    const float* WV = (const float*)d_in[3];
    const float* WO = (const float*)d_in[4];
    const float* bQ = (const float*)d_in[5];
    const float* bK = (const float*)d_in[6];
    const float* bV = (const float*)d_in[7];
    const float* bO = (const float*)d_in[8];
    float* out = (float*)d_out;

    float *q, *k, *v;
    cudaGetSymbolAddress((void**)&q, g_q);
    cudaGetSymbolAddress((void**)&k, g_k);
    cudaGetSymbolAddress((void**)&v, g_v);

    // QKV projections
    dim3 gq(BS_ / 64, H_);
    qkv_gemm<<<gq, 256>>>(x, WQ, bQ, q);
    qkv_gemm<<<gq, 256>>>(x, WK, bK, k);
    qkv_gemm<<<gq, 256>>>(x, WV, bV, v);

    // Flash attention
    const int smem_bytes = (64 * 64 + 64 * 65 + 64 * 64 + 3 * 64) * (int)sizeof(float);
    cudaFuncSetAttribute(attn_kernel, cudaFuncAttributeMaxDynamicSharedMemorySize, smem_bytes);
    dim3 ga(S_ / 64, H_, B_);
    attn_kernel<<<ga, 256, smem_bytes>>>();

    // Output projection
    dim3 gp(BS_ / 64, D_ / 64);
    out_proj<<<gp, 256>>>(WO, bO, out);
}

// round 6
// speedup vs baseline: 3.5671x; 3.5671x over previous
#include <cuda_runtime.h>
#include <math.h>

#define B_  4
#define S_  2048
#define D_  768
#define H_  12
#define E_  64
#define BS_ (B_ * S_)   // 8192

// Scratch (static device globals: allocation-free per harness rules)
__device__ float g_q[(size_t)B_ * H_ * S_ * E_];
__device__ float g_k[(size_t)B_ * H_ * S_ * E_];
__device__ float g_v[(size_t)B_ * H_ * S_ * E_];
__device__ float g_z[(size_t)BS_ * D_];

// ---------------------------------------------------------------------------
// tf32 helpers
// ---------------------------------------------------------------------------
__device__ __forceinline__ unsigned tf32cvt(float f) {
    unsigned u;
    asm("cvt.rna.tf32.f32 %0, %1;" : "=r"(u) : "f"(f));
    return u;
}

__device__ __forceinline__ void mma8(float c[4],
                                     unsigned a0, unsigned a1, unsigned a2, unsigned a3,
                                     unsigned b0, unsigned b1) {
    asm volatile(
        "mma.sync.aligned.m16n8k8.row.col.f32.tf32.tf32.f32 "
        "{%0,%1,%2,%3}, {%4,%5,%6,%7}, {%8,%9}, {%0,%1,%2,%3};\n"
        : "+f"(c[0]), "+f"(c[1]), "+f"(c[2]), "+f"(c[3])
        : "r"(a0), "r"(a1), "r"(a2), "r"(a3), "r"(b0), "r"(b1));
}

// ---------------------------------------------------------------------------
// Fused QKV projection. blockIdx.z in {0,1,2} selects Q/K/V.
// Block tile 128(M) x 64(N=E), K-tile 32. 256 threads = 8 warps (4x2).
// ---------------------------------------------------------------------------
__global__ void __launch_bounds__(256) qkv_gemm(
    const float* __restrict__ x,
    const float* __restrict__ WQ, const float* __restrict__ WK, const float* __restrict__ WV,
    const float* __restrict__ bQ, const float* __restrict__ bK, const float* __restrict__ bV,
    float* __restrict__ q, float* __restrict__ k, float* __restrict__ v)
{
    const float* W; const float* bias; float* out;
    if (blockIdx.z == 0)      { W = WQ; bias = bQ; out = q; }
    else if (blockIdx.z == 1) { W = WK; bias = bK; out = k; }
    else                      { W = WV; bias = bV; out = v; }

    __shared__ unsigned As[128][36];   // 128 rows x 32 K (pad 36)
    __shared__ unsigned Bs[32][72];    // 32 K x 64 N (pad 72)

    const int h    = blockIdx.y;
    const int row0 = blockIdx.x * 128;
    const int tid  = threadIdx.x;
    const int lane = tid & 31;
    const int wid  = tid >> 5;
    const int wm   = wid >> 1;      // 0..3
    const int wn   = wid & 1;       // 0..1

    const float* __restrict__ Wh = W + (size_t)h * D_ * E_;
    float acc[2][4][4] = {};

    for (int k0 = 0; k0 < D_; k0 += 32) {
        #pragma unroll
        for (int i = 0; i < 4; ++i) {
            int idx = tid + i * 256;
            int r   = idx >> 3;
            int c4  = (idx & 7) * 4;
            float4 v4 = *reinterpret_cast<const float4*>(&x[(size_t)(row0 + r) * D_ + k0 + c4]);
            uint4 u = { tf32cvt(v4.x), tf32cvt(v4.y), tf32cvt(v4.z), tf32cvt(v4.w) };
            *reinterpret_cast<uint4*>(&As[r][c4]) = u;
        }
        #pragma unroll
        for (int i = 0; i < 2; ++i) {
            int idx = tid + i * 256;
            int r   = idx >> 4;
            int c4  = (idx & 15) * 4;
            float4 v4 = *reinterpret_cast<const float4*>(&Wh[(size_t)(k0 + r) * E_ + c4]);
            uint4 u = { tf32cvt(v4.x), tf32cvt(v4.y), tf32cvt(v4.z), tf32cvt(v4.w) };
            *reinterpret_cast<uint4*>(&Bs[r][c4]) = u;
        }
        __syncthreads();

        #pragma unroll
        for (int kk = 0; kk < 4; ++kk) {
            const int ac = kk * 8 + (lane & 3);
            const int ar = wm * 32 + (lane >> 2);
            unsigned a[2][4];
            #pragma unroll
            for (int mt = 0; mt < 2; ++mt) {
                a[mt][0] = As[ar + mt * 16    ][ac];
                a[mt][1] = As[ar + mt * 16 + 8][ac];
                a[mt][2] = As[ar + mt * 16    ][ac + 4];
                a[mt][3] = As[ar + mt * 16 + 8][ac + 4];
            }
            const int bk = kk * 8 + (lane & 3);
            const int bn = wn * 32 + (lane >> 2);
            unsigned b[4][2];
            #pragma unroll
            for (int nt = 0; nt < 4; ++nt) {
                b[nt][0] = Bs[bk    ][bn + nt * 8];
                b[nt][1] = Bs[bk + 4][bn + nt * 8];
            }
            #pragma unroll
            for (int mt = 0; mt < 2; ++mt)
                #pragma unroll
                for (int nt = 0; nt < 4; ++nt)
                    mma8(acc[mt][nt], a[mt][0], a[mt][1], a[mt][2], a[mt][3],
                         b[nt][0], b[nt][1]);
        }
        __syncthreads();
    }

    #pragma unroll
    for (int mt = 0; mt < 2; ++mt) {
        #pragma unroll
        for (int rr = 0; rr < 2; ++rr) {
            int row = row0 + wm * 32 + mt * 16 + (lane >> 2) + rr * 8;
            int b_  = row / S_, s = row % S_;
            float* orow = out + ((size_t)(b_ * H_ + h) * S_ + s) * E_;
            #pragma unroll
            for (int nt = 0; nt < 4; ++nt) {
                int e = wn * 32 + nt * 8 + 2 * (lane & 3);
                orow[e    ] = acc[mt][nt][rr * 2    ] + bias[h * E_ + e];
                orow[e + 1] = acc[mt][nt][rr * 2 + 1] + bias[h * E_ + e + 1];
            }
        }
    }
}

// ---------------------------------------------------------------------------
// Flash attention, tf32 mma. Block = (b, h, 64-query tile), 128 threads.
// Warp w owns query rows w*16..w*16+15. Full register softmax (quad shfl).
// Dynamic smem: Qs[64][68], KPs[64][68] (K tile, then reused for P), Vs[64][72].
// Strides: 68 (=4 mod 32) conflict-free for A/B-frag reads;
//          72 (=8 mod 32) conflict-free for the P@V B-frag (row from lane&3).
// ---------------------------------------------------------------------------
#define QS_STRIDE 68
#define VS_STRIDE 72

__global__ void __launch_bounds__(128) attn_kernel()
{
    extern __shared__ unsigned sm_u[];
    unsigned* Qs  = sm_u;                       // 64*68
    unsigned* KPs = Qs + 64 * QS_STRIDE;        // 64*68
    unsigned* Vs  = KPs + 64 * QS_STRIDE;       // 64*72

    const int qt  = blockIdx.x;
    const int h   = blockIdx.y;
    const int b   = blockIdx.z;
    const int tid = threadIdx.x;
    const int lane = tid & 31;
    const int w    = tid >> 5;

    const size_t bh = ((size_t)(b * H_ + h)) * S_ * E_;

    // Load Q tile -> tf32 smem
    #pragma unroll
    for (int i = 0; i < 8; ++i) {
        int idx = tid + i * 128;          // float4 index 0..1023
        int r   = idx >> 4;
        int c4  = (idx & 15) * 4;
        float4 v4 = *reinterpret_cast<const float4*>(&g_q[bh + (size_t)(qt * 64 + r) * E_ + c4]);
        uint4 u = { tf32cvt(v4.x), tf32cvt(v4.y), tf32cvt(v4.z), tf32cvt(v4.w) };
        *reinterpret_cast<uint4*>(&Qs[r * QS_STRIDE + c4]) = u;
    }
    __syncthreads();

    float o[8][4] = {};
    float m_[2] = { -1e30f, -1e30f };
    float l_[2] = { 0.f, 0.f };

    const int ar = w * 16 + (lane >> 2);
    const float scale = 0.125f;

    for (int jt = 0; jt <= qt; ++jt) {
        // Load K, V tiles -> tf32 smem
        #pragma unroll
        for (int i = 0; i < 8; ++i) {
            int idx = tid + i * 128;
            int r   = idx >> 4;
            int c4  = (idx & 15) * 4;
            float4 kv4 = *reinterpret_cast<const float4*>(&g_k[bh + (size_t)(jt * 64 + r) * E_ + c4]);
            uint4 ku = { tf32cvt(kv4.x), tf32cvt(kv4.y), tf32cvt(kv4.z), tf32cvt(kv4.w) };
            *reinterpret_cast<uint4*>(&KPs[r * QS_STRIDE + c4]) = ku;
            float4 vv4 = *reinterpret_cast<const float4*>(&g_v[bh + (size_t)(jt * 64 + r) * E_ + c4]);
            uint4 vu = { tf32cvt(vv4.x), tf32cvt(vv4.y), tf32cvt(vv4.z), tf32cvt(vv4.w) };
            *reinterpret_cast<uint4*>(&Vs[r * VS_STRIDE + c4]) = vu;
        }
        __syncthreads();

        // S = Q K^T  (warp band 16 x 64)
        float s[8][4] = {};
        #pragma unroll
        for (int kk = 0; kk < 8; ++kk) {
            int ac = kk * 8 + (lane & 3);
            unsigned a0 = Qs[(ar    ) * QS_STRIDE + ac];
            unsigned a1 = Qs[(ar + 8) * QS_STRIDE + ac];
            unsigned a2 = Qs[(ar    ) * QS_STRIDE + ac + 4];
            unsigned a3 = Qs[(ar + 8) * QS_STRIDE + ac + 4];
            #pragma unroll
            for (int nt = 0; nt < 8; ++nt) {
                int brow = nt * 8 + (lane >> 2);
                unsigned b0 = KPs[brow * QS_STRIDE + ac];
                unsigned b1 = KPs[brow * QS_STRIDE + ac + 4];
                mma8(s[nt], a0, a1, a2, a3, b0, b1);
            }
        }

        // scale + causal mask + online softmax (quad reduction)
        const int qrow0 = qt * 64 + w * 16 + (lane >> 2);   // rows for c0/c1; +8 for c2/c3
        float mnew0 = m_[0], mnew1 = m_[1];
        #pragma unroll
        for (int nt = 0; nt < 8; ++nt) {
            int col = jt * 64 + nt * 8 + 2 * (lane & 3);
            float v0 = s[nt][0] * scale;
            float v1 = s[nt][1] * scale;
            float v2 = s[nt][2] * scale;
            float v3 = s[nt][3] * scale;
            if (jt == qt) {
                if (col     > qrow0)     v0 = -1e30f;
                if (col + 1 > qrow0)     v1 = -1e30f;
                if (col     > qrow0 + 8) v2 = -1e30f;
                if (col + 1 > qrow0 + 8) v3 = -1e30f;
            }
            s[nt][0] = v0; s[nt][1] = v1; s[nt][2] = v2; s[nt][3] = v3;
            mnew0 = fmaxf(mnew0, fmaxf(v0, v1));
            mnew1 = fmaxf(mnew1, fmaxf(v2, v3));
        }
        mnew0 = fmaxf(mnew0, __shfl_xor_sync(0xffffffffu, mnew0, 1));
        mnew0 = fmaxf(mnew0, __shfl_xor_sync(0xffffffffu, mnew0, 2));
        mnew1 = fmaxf(mnew1, __shfl_xor_sync(0xffffffffu, mnew1, 1));
        mnew1 = fmaxf(mnew1, __shfl_xor_sync(0xffffffffu, mnew1, 2));

        float f0 = __expf(m_[0] - mnew0);
        float f1 = __expf(m_[1] - mnew1);
        float sum0 = 0.f, sum1 = 0.f;
        #pragma unroll
        for (int nt = 0; nt < 8; ++nt) {
            s[nt][0] = __expf(s[nt][0] - mnew0);
            s[nt][1] = __expf(s[nt][1] - mnew0);
            s[nt][2] = __expf(s[nt][2] - mnew1);
            s[nt][3] = __expf(s[nt][3] - mnew1);
            sum0 += s[nt][0] + s[nt][1];
            sum1 += s[nt][2] + s[nt][3];
        }
        sum0 += __shfl_xor_sync(0xffffffffu, sum0, 1);
        sum0 += __shfl_xor_sync(0xffffffffu, sum0, 2);
        sum1 += __shfl_xor_sync(0xffffffffu, sum1, 1);
        sum1 += __shfl_xor_sync(0xffffffffu, sum1, 2);
        l_[0] = l_[0] * f0 + sum0;
        l_[1] = l_[1] * f1 + sum1;
        m_[0] = mnew0;
        m_[1] = mnew1;

        // rescale O accumulators
        #pragma unroll
        for (int nt = 0; nt < 8; ++nt) {
            o[nt][0] *= f0; o[nt][1] *= f0;
            o[nt][2] *= f1; o[nt][3] *= f1;
        }

        // All warps must finish reading K before P overwrites the K tile
        __syncthreads();

        // store P (tf32) into warp-private rows of KPs
        {
            int pr = w * 16 + (lane >> 2);
            #pragma unroll
            for (int nt = 0; nt < 8; ++nt) {
                int pc = nt * 8 + 2 * (lane & 3);
                KPs[(pr    ) * QS_STRIDE + pc    ] = tf32cvt(s[nt][0]);
                KPs[(pr    ) * QS_STRIDE + pc + 1] = tf32cvt(s[nt][1]);
                KPs[(pr + 8) * QS_STRIDE + pc    ] = tf32cvt(s[nt][2]);
                KPs[(pr + 8) * QS_STRIDE + pc + 1] = tf32cvt(s[nt][3]);
            }
        }
        __syncwarp();   // P@V reads only this warp's rows of KPs

        // O += P @ V
        #pragma unroll
        for (int kk = 0; kk < 8; ++kk) {
            int ac = kk * 8 + (lane & 3);
            unsigned a0 = KPs[(ar    ) * QS_STRIDE + ac];
            unsigned a1 = KPs[(ar + 8) * QS_STRIDE + ac];
            unsigned a2 = KPs[(ar    ) * QS_STRIDE + ac + 4];
            unsigned a3 = KPs[(ar + 8) * QS_STRIDE + ac + 4];
            #pragma unroll
            for (int nt = 0; nt < 8; ++nt) {
                int bn = nt * 8 + (lane >> 2);
                unsigned b0 = Vs[(kk * 8 + (lane & 3)    ) * VS_STRIDE + bn];
                unsigned b1 = Vs[(kk * 8 + (lane & 3) + 4) * VS_STRIDE + bn];
                mma8(o[nt], a0, a1, a2, a3, b0, b1);
            }
        }
        __syncthreads();   // guard K/V reload and P overwrite next iter
    }

    // normalize + write z as [bs][h*64+e]
    float inv0 = 1.0f / l_[0];
    float inv1 = 1.0f / l_[1];
    int qr = qt * 64 + w * 16 + (lane >> 2);
    #pragma unroll
    for (int nt = 0; nt < 8; ++nt) {
        int e = nt * 8 + 2 * (lane & 3);
        size_t base0 = (size_t)(b * S_ + qr) * D_ + h * E_ + e;
        size_t base1 = (size_t)(b * S_ + qr + 8) * D_ + h * E_ + e;
        g_z[base0    ] = o[nt][0] * inv0;
        g_z[base0 + 1] = o[nt][1] * inv0;
        g_z[base1    ] = o[nt][2] * inv1;
        g_z[base1 + 1] = o[nt][3] * inv1;
    }
}

// ---------------------------------------------------------------------------
// Output projection: [8192 x 768] = z[8192 x 768] @ Wo[768 x 768] + bO
// ---------------------------------------------------------------------------
__global__ void __launch_bounds__(256) out_proj(
    const float* __restrict__ Wo, const float* __restrict__ bO,
    float* __restrict__ out)
{
    __shared__ unsigned As[128][36];
    __shared__ unsigned Bs[32][72];

    const int n0   = blockIdx.y * 64;
    const int row0 = blockIdx.x * 128;
    const int tid  = threadIdx.x;
    const int lane = tid & 31;
    const int wid  = tid >> 5;
    const int wm   = wid >> 1;
    const int wn   = wid & 1;

    float acc[2][4][4] = {};

    for (int k0 = 0; k0 < D_; k0 += 32) {
        #pragma unroll
        for (int i = 0; i < 4; ++i) {
            int idx = tid + i * 256;
            int r   = idx >> 3;
            int c4  = (idx & 7) * 4;
            float4 v4 = *reinterpret_cast<const float4*>(&g_z[(size_t)(row0 + r) * D_ + k0 + c4]);
            uint4 u = { tf32cvt(v4.x), tf32cvt(v4.y), tf32cvt(v4.z), tf32cvt(v4.w) };
            *reinterpret_cast<uint4*>(&As[r][c4]) = u;
        }
        #pragma unroll
        for (int i = 0; i < 2; ++i) {
            int idx = tid + i * 256;
            int r   = idx >> 4;
            int c4  = (idx & 15) * 4;
            float4 v4 = *reinterpret_cast<const float4*>(&Wo[(size_t)(k0 + r) * D_ + n0 + c4]);
            uint4 u = { tf32cvt(v4.x), tf32cvt(v4.y), tf32cvt(v4.z), tf32cvt(v4.w) };
            *reinterpret_cast<uint4*>(&Bs[r][c4]) = u;
        }
        __syncthreads();

        #pragma unroll
        for (int kk = 0; kk < 4; ++kk) {
            const int ac = kk * 8 + (lane & 3);
            const int ar = wm * 32 + (lane >> 2);
            unsigned a[2][4];
            #pragma unroll
            for (int mt = 0; mt < 2; ++mt) {
                a[mt][0] = As[ar + mt * 16    ][ac];
                a[mt][1] = As[ar + mt * 16 + 8][ac];
                a[mt][2] = As[ar + mt * 16    ][ac + 4];
                a[mt][3] = As[ar + mt * 16 + 8][ac + 4];
            }
            const int bk = kk * 8 + (lane & 3);
            const int bn = wn * 32 + (lane >> 2);
            unsigned b[4][2];
            #pragma unroll
            for (int nt = 0; nt < 4; ++nt) {
                b[nt][0] = Bs[bk    ][bn + nt * 8];
                b[nt][1] = Bs[bk + 4][bn + nt * 8];
            }
            #pragma unroll
            for (int mt = 0; mt < 2; ++mt)
                #pragma unroll
                for (int nt = 0; nt < 4; ++nt)
                    mma8(acc[mt][nt], a[mt][0], a[mt][1], a[mt][2], a[mt][3],
                         b[nt][0], b[nt][1]);
        }
        __syncthreads();
    }

    #pragma unroll
    for (int mt = 0; mt < 2; ++mt) {
        #pragma unroll
        for (int rr = 0; rr < 2; ++rr) {
            int row = row0 + wm * 32 + mt * 16 + (lane >> 2) + rr * 8;
            #pragma unroll
            for (int nt = 0; nt < 4; ++nt) {
                int d = n0 + wn * 32 + nt * 8 + 2 * (lane & 3);
                out[(size_t)row * D_ + d    ] = acc[mt][nt][rr * 2    ] + bO[d];
                out[(size_t)row * D_ + d + 1] = acc[mt][nt][rr * 2 + 1] + bO[d + 1];
            }
        }
    }
}

// ---------------------------------------------------------------------------
extern "C" void kernel_launch(void* const* d_in, const int* in_sizes, int n_in,
                              void* d_out, int out_size)
{
    const float* x  = (const float*)d_in[0];
    const float* WQ = (const float*)d_in[1];
    const float* WK = (const float*)d_in[2];
    const float* WV = (const float*)d_in[3];
    const float* WO = (const float*)d_in[4];
    const float* bQ = (const float*)d_in[5];
    const float* bK = (const float*)d_in[6];
    const float* bV = (const float*)d_in[7];
    const float* bO = (const float*)d_in[8];
    float* out = (float*)d_out;

    float *q, *k, *v;
    cudaGetSymbolAddress((void**)&q, g_q);
    cudaGetSymbolAddress((void**)&k, g_k);
    cudaGetSymbolAddress((void**)&v, g_v);

    // Fused QKV projections
    dim3 gq(BS_ / 128, H_, 3);
    qkv_gemm<<<gq, 256>>>(x, WQ, WK, WV, bQ, bK, bV, q, k, v);

    // Flash attention (tf32 mma), dynamic smem
    const int attn_smem = 64 * (QS_STRIDE + QS_STRIDE + VS_STRIDE) * (int)sizeof(unsigned);
    cudaFuncSetAttribute(attn_kernel, cudaFuncAttributeMaxDynamicSharedMemorySize, attn_smem);
    dim3 ga(S_ / 64, H_, B_);
    attn_kernel<<<ga, 128, attn_smem>>>();

    // Output projection
    dim3 gp(BS_ / 128, D_ / 64);
    out_proj<<<gp, 256>>>(WO, bO, out);
}